// round 8
// baseline (speedup 1.0000x reference)
#include <cuda_runtime.h>
#include <cuda_bf16.h>
#include <cstdint>

#define EPSF 1e-12f

// Problem constants: N=8, T=2048, D=512, K=64, M=N*T=16384
// Scratch (device globals; allocation is forbidden). No pre-zeroing needed:
// partials are plainly overwritten each call; counters self-reset each call.
__device__ __nv_bfloat16 g_vpb[8 * 64 * 16 * 512];  // VLAD partials [n][k][p][d] (8 MB)
__device__ float g_asump[16 * 8 * 64];              // asum partials [tc][n][k]
__device__ int   g_cnt[8];                          // producer arrivals per n
__device__ int   g_done[8];                         // consumer completions per n

// Shared-memory geometry (bf16 elements)
#define XS_STR 520   // 128 x 520 : x tile [row][d]
#define WS_STR 520   // 64  x 520 : W tile [k][d]
#define AS_STR 72    // 128 x 72  : a' tile [t][k]
#define SMEM_BYTES (size_t)((128 * XS_STR + 64 * WS_STR + 128 * AS_STR) * 2)

// ---------------------------------------------------------------------------
__device__ __forceinline__ uint32_t smem_u32(const void* p) {
    return (uint32_t)__cvta_generic_to_shared(p);
}
__device__ __forceinline__ void ldsm_x4(uint32_t addr, uint32_t& r0, uint32_t& r1,
                                        uint32_t& r2, uint32_t& r3) {
    asm volatile("ldmatrix.sync.aligned.m8n8.x4.shared.b16 {%0,%1,%2,%3}, [%4];"
                 : "=r"(r0), "=r"(r1), "=r"(r2), "=r"(r3) : "r"(addr));
}
__device__ __forceinline__ void ldsm_x4t(uint32_t addr, uint32_t& r0, uint32_t& r1,
                                         uint32_t& r2, uint32_t& r3) {
    asm volatile("ldmatrix.sync.aligned.m8n8.x4.trans.shared.b16 {%0,%1,%2,%3}, [%4];"
                 : "=r"(r0), "=r"(r1), "=r"(r2), "=r"(r3) : "r"(addr));
}
__device__ __forceinline__ void mma16816(float c[4], uint32_t a0, uint32_t a1,
                                         uint32_t a2, uint32_t a3,
                                         uint32_t b0, uint32_t b1) {
    asm volatile(
        "mma.sync.aligned.m16n8k16.row.col.f32.bf16.bf16.f32 "
        "{%0,%1,%2,%3}, {%4,%5,%6,%7}, {%8,%9}, {%0,%1,%2,%3};"
        : "+f"(c[0]), "+f"(c[1]), "+f"(c[2]), "+f"(c[3])
        : "r"(a0), "r"(a1), "r"(a2), "r"(a3), "r"(b0), "r"(b1));
}
__device__ __forceinline__ __nv_bfloat162 u2bf2(uint32_t u) {
    __nv_bfloat162 r; *(uint32_t*)&r = u; return r;
}
__device__ __forceinline__ uint32_t bf22u(__nv_bfloat162 v) {
    return *(uint32_t*)&v;
}
__device__ __forceinline__ uint32_t pack_bf2(float a, float b) {
    __nv_bfloat162 t = __floats2bfloat162_rn(a, b);
    return *(uint32_t*)&t;
}

// ---------------------------------------------------------------------------
// Producer body: fused x->bf16 + row L2-norm + logits MMA + softmax + VLAD MMA.
// Block owns rows [n*2048 + tc*128, +128).  256 threads (8 warps).
// ---------------------------------------------------------------------------
__device__ void producer(int tc, int n,
                         const float* __restrict__ x, const float* __restrict__ W,
                         const float* __restrict__ bias, __nv_bfloat16* sm) {
    __nv_bfloat16 (*xs)[XS_STR] = (__nv_bfloat16 (*)[XS_STR])sm;
    __nv_bfloat16 (*ws)[WS_STR] = (__nv_bfloat16 (*)[WS_STR])(sm + 128 * XS_STR);
    __nv_bfloat16 (*as)[AS_STR] = (__nv_bfloat16 (*)[AS_STR])(sm + 128 * XS_STR + 64 * WS_STR);

    __shared__ float rowinv[128];
    __shared__ float sbias[64];
    __shared__ float sAsum[64];

    const int tid = threadIdx.x;
    const int w   = tid >> 5;
    const int l   = tid & 31;
    const size_t m0 = (size_t)n * 2048 + tc * 128;

    if (tid < 64) { sbias[tid] = bias[tid]; sAsum[tid] = 0.f; }

    // ---- Phase 1: load + convert (warp-per-16-rows, fully coalesced) ----
    {
        const float4* xg = (const float4*)(x + m0 * 512);
#pragma unroll 2
        for (int rr = 0; rr < 16; rr++) {
            const int r = w * 16 + rr;
            float4 v[4];
#pragma unroll
            for (int cb = 0; cb < 4; cb++)
                v[cb] = xg[(size_t)r * 128 + cb * 32 + l];
            float sq = 0.f;
#pragma unroll
            for (int cb = 0; cb < 4; cb++) {
                sq += v[cb].x * v[cb].x + v[cb].y * v[cb].y
                    + v[cb].z * v[cb].z + v[cb].w * v[cb].w;
                uint2 u = make_uint2(pack_bf2(v[cb].x, v[cb].y),
                                     pack_bf2(v[cb].z, v[cb].w));
                *(uint2*)&xs[r][(cb * 32 + l) * 4] = u;  // single STS.64
            }
            sq += __shfl_xor_sync(~0u, sq, 16);
            sq += __shfl_xor_sync(~0u, sq, 8);
            sq += __shfl_xor_sync(~0u, sq, 4);
            sq += __shfl_xor_sync(~0u, sq, 2);
            sq += __shfl_xor_sync(~0u, sq, 1);
            if (l == 0) rowinv[r] = 1.f / fmaxf(sqrtf(sq), EPSF);
        }
        const float4* wg = (const float4*)W;
#pragma unroll 2
        for (int rr = 0; rr < 8; rr++) {
            const int r = w * 8 + rr;
            float4 v[4];
#pragma unroll
            for (int cb = 0; cb < 4; cb++)
                v[cb] = wg[(size_t)r * 128 + cb * 32 + l];
#pragma unroll
            for (int cb = 0; cb < 4; cb++) {
                uint2 u = make_uint2(pack_bf2(v[cb].x, v[cb].y),
                                     pack_bf2(v[cb].z, v[cb].w));
                *(uint2*)&ws[r][(cb * 32 + l) * 4] = u;
            }
        }
    }
    __syncthreads();

    // ---- Phase 2: logits MMA  C[128 m x 64 k] over D=512 ----
    const int m0w = w * 16;
    const int a_row  = (l & 7) + ((l >> 3) & 1) * 8;
    const int a_koff = (l >> 4) * 8;
    const int b_row  = ((l >> 4) * 8) + (l & 7);
    const int b_koff = ((l >> 3) & 1) * 8;

    float acc[8][4];
#pragma unroll
    for (int i = 0; i < 8; i++)
#pragma unroll
        for (int j = 0; j < 4; j++) acc[i][j] = 0.f;

#pragma unroll 4
    for (int ks = 0; ks < 32; ks++) {
        const int k0 = ks * 16;
        uint32_t a0, a1, a2, a3;
        ldsm_x4(smem_u32(&xs[m0w + a_row][k0 + a_koff]), a0, a1, a2, a3);
#pragma unroll
        for (int nf2 = 0; nf2 < 4; nf2++) {
            uint32_t b0, b1, b2, b3;
            ldsm_x4(smem_u32(&ws[nf2 * 16 + b_row][k0 + b_koff]), b0, b1, b2, b3);
            mma16816(acc[nf2 * 2],     a0, a1, a2, a3, b0, b1);
            mma16816(acc[nf2 * 2 + 1], a0, a1, a2, a3, b2, b3);
        }
    }

    // ---- Phase 3: register softmax (row of 64 lives in 4 lanes sharing g) ----
    {
        const int g  = l >> 2;
        const int c2 = (l & 3) * 2;
        const int r0 = m0w + g, r1 = r0 + 8;
        const float inv0 = rowinv[r0], inv1 = rowinv[r1];

        float L0[16], L1[16];
#pragma unroll
        for (int nf = 0; nf < 8; nf++) {
            const int col = nf * 8 + c2;
            L0[2 * nf]     = acc[nf][0] * inv0 + sbias[col];
            L0[2 * nf + 1] = acc[nf][1] * inv0 + sbias[col + 1];
            L1[2 * nf]     = acc[nf][2] * inv1 + sbias[col];
            L1[2 * nf + 1] = acc[nf][3] * inv1 + sbias[col + 1];
        }
        float mx0 = -1e30f, mx1 = -1e30f;
#pragma unroll
        for (int j = 0; j < 16; j++) { mx0 = fmaxf(mx0, L0[j]); mx1 = fmaxf(mx1, L1[j]); }
        mx0 = fmaxf(mx0, __shfl_xor_sync(~0u, mx0, 1));
        mx0 = fmaxf(mx0, __shfl_xor_sync(~0u, mx0, 2));
        mx1 = fmaxf(mx1, __shfl_xor_sync(~0u, mx1, 1));
        mx1 = fmaxf(mx1, __shfl_xor_sync(~0u, mx1, 2));
        float s0 = 0.f, s1 = 0.f;
#pragma unroll
        for (int j = 0; j < 16; j++) {
            L0[j] = __expf(L0[j] - mx0); s0 += L0[j];
            L1[j] = __expf(L1[j] - mx1); s1 += L1[j];
        }
        s0 += __shfl_xor_sync(~0u, s0, 1); s0 += __shfl_xor_sync(~0u, s0, 2);
        s1 += __shfl_xor_sync(~0u, s1, 1); s1 += __shfl_xor_sync(~0u, s1, 2);
        const float rcp0 = 1.f / s0, rcp1 = 1.f / s1;

        float cs[16];
#pragma unroll
        for (int j = 0; j < 16; j++) {
            L0[j] *= rcp0; L1[j] *= rcp1;          // a values (exact fp32)
            cs[j] = L0[j] + L1[j];
        }
#pragma unroll
        for (int j = 0; j < 16; j++) {
            cs[j] += __shfl_xor_sync(~0u, cs[j], 4);
            cs[j] += __shfl_xor_sync(~0u, cs[j], 8);
            cs[j] += __shfl_xor_sync(~0u, cs[j], 16);
        }
        if (l < 4) {
#pragma unroll
            for (int nf = 0; nf < 8; nf++) {
                const int col = nf * 8 + c2;
                atomicAdd(&sAsum[col],     cs[2 * nf]);        // smem atomics only
                atomicAdd(&sAsum[col + 1], cs[2 * nf + 1]);
            }
        }
#pragma unroll
        for (int nf = 0; nf < 8; nf++) {
            const int col = nf * 8 + c2;
            *(__nv_bfloat162*)&as[r0][col] =
                __floats2bfloat162_rn(L0[2 * nf] * inv0, L0[2 * nf + 1] * inv0);
            *(__nv_bfloat162*)&as[r1][col] =
                __floats2bfloat162_rn(L1[2 * nf] * inv1, L1[2 * nf + 1] * inv1);
        }
    }
    __syncthreads();
    if (tid < 64)  // plain (non-atomic) asum partial store
        g_asump[(tc * 8 + n) * 64 + tid] = sAsum[tid];

    // ---- Phase 4: VLAD MMA  C[64 k x 512 d] = a'^T (64x128) * xs (128x512) ----
    const int wm  = (w & 3) * 16;        // cluster rows
    const int wn2 = (w >> 2) * 64;       // d sub-column within 128-wide tile
    const int at_row = ((l >> 4) * 8) + (l & 7);
    const int at_col = ((l >> 3) & 1) * 8;
    const int bt_row = (((l >> 3) & 1) * 8) + (l & 7);
    const int bt_col = (l >> 4) * 8;

    uint32_t ar[8][4];
#pragma unroll
    for (int ts = 0; ts < 8; ts++)
        ldsm_x4t(smem_u32(&as[ts * 16 + at_row][wm + at_col]),
                 ar[ts][0], ar[ts][1], ar[ts][2], ar[ts][3]);

    const int g  = l >> 2;
    const int c2 = (l & 3) * 2;
    const size_t kn0 = (size_t)n * 64;

#pragma unroll
    for (int dt = 0; dt < 4; dt++) {
        const int dbase = dt * 128 + wn2;
        float vacc[8][4];
#pragma unroll
        for (int i = 0; i < 8; i++)
#pragma unroll
            for (int j = 0; j < 4; j++) vacc[i][j] = 0.f;

#pragma unroll
        for (int ts = 0; ts < 8; ts++) {
            const int kt = ts * 16;
#pragma unroll
            for (int nf2 = 0; nf2 < 4; nf2++) {
                uint32_t b0, b1, b2, b3;
                ldsm_x4t(smem_u32(&xs[kt + bt_row][dbase + nf2 * 16 + bt_col]),
                         b0, b1, b2, b3);
                mma16816(vacc[nf2 * 2],     ar[ts][0], ar[ts][1], ar[ts][2], ar[ts][3], b0, b1);
                mma16816(vacc[nf2 * 2 + 1], ar[ts][0], ar[ts][1], ar[ts][2], ar[ts][3], b2, b3);
            }
        }
        // bf16 partial stores, layout [n][k][p=tc][d]
#pragma unroll
        for (int nf = 0; nf < 8; nf++) {
            const int col = dbase + nf * 8 + c2;
            *(__nv_bfloat162*)&g_vpb[(((kn0 + wm + g) * 16 + tc) << 9) + col] =
                __floats2bfloat162_rn(vacc[nf][0], vacc[nf][1]);
            *(__nv_bfloat162*)&g_vpb[(((kn0 + wm + g + 8) * 16 + tc) << 9) + col] =
                __floats2bfloat162_rn(vacc[nf][2], vacc[nf][3]);
        }
    }

    // ---- signal: this tc-chunk's partials for n are globally visible ----
    __threadfence();
    __syncthreads();
    if (tid == 0) atomicAdd(&g_cnt[n], 1);
}

// ---------------------------------------------------------------------------
// Consumer body: finalize 4 rows (one row-group). 64 threads per row,
// each thread owns 8 contiguous d: 16x LDG.128 of bf16 partials, packed
// HADD2 tree, v -= asum*c, intra L2 norm, analytic global 1/8, write out.
// ---------------------------------------------------------------------------
__device__ void consumer(int rg, const float* __restrict__ cent,
                         float* __restrict__ out) {
    __shared__ float wsum[4][2];
    __shared__ float s_sh[4];

    const int tid = threadIdx.x;
    const int w   = tid >> 5;
    const int l   = tid & 31;
    const int rb  = w >> 1;          // row within group (0..3)
    const int wr  = w & 1;           // warp within row (0..1)
    const int row = rg * 4 + rb;     // n*64+k
    const int k   = row & 63;
    const int n   = row >> 6;

    // wait for all 16 producers of this n
    if (tid == 0) {
        while (atomicAdd(&g_cnt[n], 0) < 16) __nanosleep(128);
    }
    __syncthreads();
    __threadfence();   // acquire: order partial reads after the counter read

    // asum reduce (16 partials) on the first warp of each row
    if (wr == 0) {
        float a = (l < 16) ? g_asump[(l * 8 + n) * 64 + k] : 0.f;
        a += __shfl_xor_sync(~0u, a, 8);
        a += __shfl_xor_sync(~0u, a, 4);
        a += __shfl_xor_sync(~0u, a, 2);
        a += __shfl_xor_sync(~0u, a, 1);
        if (l == 0) s_sh[rb] = a;
    }

    const int ei = wr * 32 + l;                       // uint4 index (8 bf16)
    const uint4* base = (const uint4*)(g_vpb + (size_t)row * 16 * 512);
    uint4 d[16];
#pragma unroll
    for (int p = 0; p < 16; p++) d[p] = base[p * 64 + ei];

    // packed bf16x2 pairwise reduction tree
#pragma unroll
    for (int step = 8; step > 0; step >>= 1)
#pragma unroll
        for (int p = 0; p < 8; p++) {
            if (p < step) {
                d[p].x = bf22u(__hadd2(u2bf2(d[p].x), u2bf2(d[p + step].x)));
                d[p].y = bf22u(__hadd2(u2bf2(d[p].y), u2bf2(d[p + step].y)));
                d[p].z = bf22u(__hadd2(u2bf2(d[p].z), u2bf2(d[p + step].z)));
                d[p].w = bf22u(__hadd2(u2bf2(d[p].w), u2bf2(d[p + step].w)));
            }
        }

    float v[8];
    {
        const float2 f0 = __bfloat1622float2(u2bf2(d[0].x));
        const float2 f1 = __bfloat1622float2(u2bf2(d[0].y));
        const float2 f2 = __bfloat1622float2(u2bf2(d[0].z));
        const float2 f3 = __bfloat1622float2(u2bf2(d[0].w));
        v[0] = f0.x; v[1] = f0.y; v[2] = f1.x; v[3] = f1.y;
        v[4] = f2.x; v[5] = f2.y; v[6] = f3.x; v[7] = f3.y;
    }

    __syncthreads();
    const float s = s_sh[rb];
    const float4 c0 = *(const float4*)(cent + (size_t)k * 512 + ei * 8);
    const float4 c1 = *(const float4*)(cent + (size_t)k * 512 + ei * 8 + 4);
    v[0] -= s * c0.x; v[1] -= s * c0.y; v[2] -= s * c0.z; v[3] -= s * c0.w;
    v[4] -= s * c1.x; v[5] -= s * c1.y; v[6] -= s * c1.z; v[7] -= s * c1.w;

    float sq = 0.f;
#pragma unroll
    for (int j = 0; j < 8; j++) sq += v[j] * v[j];
    sq += __shfl_xor_sync(~0u, sq, 16);
    sq += __shfl_xor_sync(~0u, sq, 8);
    sq += __shfl_xor_sync(~0u, sq, 4);
    sq += __shfl_xor_sync(~0u, sq, 2);
    sq += __shfl_xor_sync(~0u, sq, 1);
    if (l == 0) wsum[rb][wr] = sq;
    __syncthreads();

    const float tot = wsum[rb][0] + wsum[rb][1];
    const float inv = 0.125f / fmaxf(sqrtf(tot), EPSF);  // intra-norm * global 1/8

    float4 o0, o1;
    o0.x = v[0] * inv; o0.y = v[1] * inv; o0.z = v[2] * inv; o0.w = v[3] * inv;
    o1.x = v[4] * inv; o1.y = v[5] * inv; o1.z = v[6] * inv; o1.w = v[7] * inv;
    float* op = out + (size_t)row * 512 + ei * 8;
    *(float4*)op       = o0;
    *(float4*)(op + 4) = o1;

    // self-reset counters for the next (graph-replayed) call
    __syncthreads();
    if (tid == 0) {
        int old = atomicAdd(&g_done[n], 1);
        if (old == 15) {            // last consumer block of this n
            atomicExch(&g_done[n], 0);
            atomicExch(&g_cnt[n], 0);
        }
    }
}

// ---------------------------------------------------------------------------
// Single persistent-style kernel: bids 0..127 produce, 128..255 consume.
// Producers all fit in wave 1 (128 < 148 SMs) -> no deadlock; consumers
// start per-n as soon as that n's 16 producers finish (overlap).
// ---------------------------------------------------------------------------
__global__ __launch_bounds__(256) void netvlad_kernel(
        const float* __restrict__ x, const float* __restrict__ W,
        const float* __restrict__ bias, const float* __restrict__ cent,
        float* __restrict__ out) {
    extern __shared__ __align__(16) __nv_bfloat16 sm[];
    const int bid = blockIdx.x;
    if (bid < 128) {
        producer(bid >> 3, bid & 7, x, W, bias, sm);
    } else {
        consumer(bid - 128, cent, out);
    }
}

// ---------------------------------------------------------------------------
extern "C" void kernel_launch(void* const* d_in, const int* in_sizes, int n_in,
                              void* d_out, int out_size) {
    const float* x    = (const float*)d_in[0];   // [8,2048,512]
    const float* W    = (const float*)d_in[1];   // [64,512]
    const float* b    = (const float*)d_in[2];   // [64]
    const float* cent = (const float*)d_in[3];   // [64,512]
    float* out = (float*)d_out;                  // [8, 64*512]

    cudaFuncSetAttribute(netvlad_kernel,
                         cudaFuncAttributeMaxDynamicSharedMemorySize,
                         (int)SMEM_BYTES);

    netvlad_kernel<<<256, 256, SMEM_BYTES>>>(x, W, b, cent, out);
}

// round 9
// speedup vs baseline: 1.0687x; 1.0687x over previous
#include <cuda_runtime.h>
#include <cuda_bf16.h>
#include <cstdint>

#define EPSF 1e-12f

// Problem constants: N=8, T=2048, D=512, K=64, M=N*T=16384
// Scratch (device globals; allocation is forbidden). No pre-zeroing needed:
// partials are plainly overwritten each call; counters self-reset each call.
__device__ __nv_bfloat16 g_vpb[8 * 64 * 16 * 512];  // VLAD partials [n][k][p][d] (8 MB)
__device__ float g_asump[16 * 8 * 64];              // asum partials [tc][n][k]
__device__ int   g_cnt[8];                          // producer arrivals per n
__device__ int   g_done[8];                         // finalize completions per n

// Shared-memory geometry (bf16 elements)
#define XS_STR 520   // 128 x 520 : x tile [row][d]
#define WS_STR 520   // 64  x 520 : W tile [k][d]
#define AS_STR 72    // 128 x 72  : a' tile [t][k]
#define SMEM_BYTES (size_t)((128 * XS_STR + 64 * WS_STR + 128 * AS_STR) * 2)

// ---------------------------------------------------------------------------
__device__ __forceinline__ uint32_t smem_u32(const void* p) {
    return (uint32_t)__cvta_generic_to_shared(p);
}
__device__ __forceinline__ void ldsm_x4(uint32_t addr, uint32_t& r0, uint32_t& r1,
                                        uint32_t& r2, uint32_t& r3) {
    asm volatile("ldmatrix.sync.aligned.m8n8.x4.shared.b16 {%0,%1,%2,%3}, [%4];"
                 : "=r"(r0), "=r"(r1), "=r"(r2), "=r"(r3) : "r"(addr));
}
__device__ __forceinline__ void ldsm_x4t(uint32_t addr, uint32_t& r0, uint32_t& r1,
                                         uint32_t& r2, uint32_t& r3) {
    asm volatile("ldmatrix.sync.aligned.m8n8.x4.trans.shared.b16 {%0,%1,%2,%3}, [%4];"
                 : "=r"(r0), "=r"(r1), "=r"(r2), "=r"(r3) : "r"(addr));
}
__device__ __forceinline__ void mma16816(float c[4], uint32_t a0, uint32_t a1,
                                         uint32_t a2, uint32_t a3,
                                         uint32_t b0, uint32_t b1) {
    asm volatile(
        "mma.sync.aligned.m16n8k16.row.col.f32.bf16.bf16.f32 "
        "{%0,%1,%2,%3}, {%4,%5,%6,%7}, {%8,%9}, {%0,%1,%2,%3};"
        : "+f"(c[0]), "+f"(c[1]), "+f"(c[2]), "+f"(c[3])
        : "r"(a0), "r"(a1), "r"(a2), "r"(a3), "r"(b0), "r"(b1));
}
__device__ __forceinline__ __nv_bfloat162 u2bf2(uint32_t u) {
    __nv_bfloat162 r; *(uint32_t*)&r = u; return r;
}
__device__ __forceinline__ uint32_t bf22u(__nv_bfloat162 v) {
    return *(uint32_t*)&v;
}
__device__ __forceinline__ uint32_t pack_bf2(float a, float b) {
    __nv_bfloat162 t = __floats2bfloat162_rn(a, b);
    return *(uint32_t*)&t;
}

// ---------------------------------------------------------------------------
// Single kernel, grid 128 (one wave): block (tc,n) produces its 128-row chunk,
// signals, then finalizes 4 rows of its n once all 16 chunks of n arrived.
// ---------------------------------------------------------------------------
__global__ __launch_bounds__(256) void netvlad_kernel(
        const float* __restrict__ x, const float* __restrict__ W,
        const float* __restrict__ bias, const float* __restrict__ cent,
        float* __restrict__ out) {
    extern __shared__ __align__(16) __nv_bfloat16 sm[];
    __nv_bfloat16 (*xs)[XS_STR] = (__nv_bfloat16 (*)[XS_STR])sm;
    __nv_bfloat16 (*ws)[WS_STR] = (__nv_bfloat16 (*)[WS_STR])(sm + 128 * XS_STR);
    __nv_bfloat16 (*as)[AS_STR] = (__nv_bfloat16 (*)[AS_STR])(sm + 128 * XS_STR + 64 * WS_STR);

    __shared__ float rowinv[128];
    __shared__ float sbias[64];
    __shared__ float sAsum[64];

    const int tid = threadIdx.x;
    const int w   = tid >> 5;
    const int l   = tid & 31;
    const int tc  = blockIdx.x >> 3;
    const int n   = blockIdx.x & 7;
    const size_t m0 = (size_t)n * 2048 + tc * 128;

    if (tid < 64) { sbias[tid] = bias[tid]; sAsum[tid] = 0.f; }

    // ==================== PRODUCER ====================
    // ---- Phase 1: load + convert (warp-per-16-rows, fully coalesced) ----
    {
        const float4* xg = (const float4*)(x + m0 * 512);
#pragma unroll 2
        for (int rr = 0; rr < 16; rr++) {
            const int r = w * 16 + rr;
            float4 v[4];
#pragma unroll
            for (int cb = 0; cb < 4; cb++)
                v[cb] = xg[(size_t)r * 128 + cb * 32 + l];
            float sq = 0.f;
#pragma unroll
            for (int cb = 0; cb < 4; cb++) {
                sq += v[cb].x * v[cb].x + v[cb].y * v[cb].y
                    + v[cb].z * v[cb].z + v[cb].w * v[cb].w;
                uint2 u = make_uint2(pack_bf2(v[cb].x, v[cb].y),
                                     pack_bf2(v[cb].z, v[cb].w));
                *(uint2*)&xs[r][(cb * 32 + l) * 4] = u;  // single STS.64
            }
            sq += __shfl_xor_sync(~0u, sq, 16);
            sq += __shfl_xor_sync(~0u, sq, 8);
            sq += __shfl_xor_sync(~0u, sq, 4);
            sq += __shfl_xor_sync(~0u, sq, 2);
            sq += __shfl_xor_sync(~0u, sq, 1);
            if (l == 0) rowinv[r] = 1.f / fmaxf(sqrtf(sq), EPSF);
        }
        const float4* wg = (const float4*)W;
#pragma unroll 2
        for (int rr = 0; rr < 8; rr++) {
            const int r = w * 8 + rr;
            float4 v[4];
#pragma unroll
            for (int cb = 0; cb < 4; cb++)
                v[cb] = wg[(size_t)r * 128 + cb * 32 + l];
#pragma unroll
            for (int cb = 0; cb < 4; cb++) {
                uint2 u = make_uint2(pack_bf2(v[cb].x, v[cb].y),
                                     pack_bf2(v[cb].z, v[cb].w));
                *(uint2*)&ws[r][(cb * 32 + l) * 4] = u;
            }
        }
    }
    __syncthreads();

    // ---- Phase 2: logits MMA  C[128 m x 64 k] over D=512 ----
    const int m0w = w * 16;
    const int a_row  = (l & 7) + ((l >> 3) & 1) * 8;
    const int a_koff = (l >> 4) * 8;
    const int b_row  = ((l >> 4) * 8) + (l & 7);
    const int b_koff = ((l >> 3) & 1) * 8;

    float acc[8][4];
#pragma unroll
    for (int i = 0; i < 8; i++)
#pragma unroll
        for (int j = 0; j < 4; j++) acc[i][j] = 0.f;

#pragma unroll 4
    for (int ks = 0; ks < 32; ks++) {
        const int k0 = ks * 16;
        uint32_t a0, a1, a2, a3;
        ldsm_x4(smem_u32(&xs[m0w + a_row][k0 + a_koff]), a0, a1, a2, a3);
#pragma unroll
        for (int nf2 = 0; nf2 < 4; nf2++) {
            uint32_t b0, b1, b2, b3;
            ldsm_x4(smem_u32(&ws[nf2 * 16 + b_row][k0 + b_koff]), b0, b1, b2, b3);
            mma16816(acc[nf2 * 2],     a0, a1, a2, a3, b0, b1);
            mma16816(acc[nf2 * 2 + 1], a0, a1, a2, a3, b2, b3);
        }
    }

    // ---- Phase 3: register softmax (row of 64 lives in 4 lanes sharing g) ----
    {
        const int g  = l >> 2;
        const int c2 = (l & 3) * 2;
        const int r0 = m0w + g, r1 = r0 + 8;
        const float inv0 = rowinv[r0], inv1 = rowinv[r1];

        float L0[16], L1[16];
#pragma unroll
        for (int nf = 0; nf < 8; nf++) {
            const int col = nf * 8 + c2;
            L0[2 * nf]     = acc[nf][0] * inv0 + sbias[col];
            L0[2 * nf + 1] = acc[nf][1] * inv0 + sbias[col + 1];
            L1[2 * nf]     = acc[nf][2] * inv1 + sbias[col];
            L1[2 * nf + 1] = acc[nf][3] * inv1 + sbias[col + 1];
        }
        float mx0 = -1e30f, mx1 = -1e30f;
#pragma unroll
        for (int j = 0; j < 16; j++) { mx0 = fmaxf(mx0, L0[j]); mx1 = fmaxf(mx1, L1[j]); }
        mx0 = fmaxf(mx0, __shfl_xor_sync(~0u, mx0, 1));
        mx0 = fmaxf(mx0, __shfl_xor_sync(~0u, mx0, 2));
        mx1 = fmaxf(mx1, __shfl_xor_sync(~0u, mx1, 1));
        mx1 = fmaxf(mx1, __shfl_xor_sync(~0u, mx1, 2));
        float s0 = 0.f, s1 = 0.f;
#pragma unroll
        for (int j = 0; j < 16; j++) {
            L0[j] = __expf(L0[j] - mx0); s0 += L0[j];
            L1[j] = __expf(L1[j] - mx1); s1 += L1[j];
        }
        s0 += __shfl_xor_sync(~0u, s0, 1); s0 += __shfl_xor_sync(~0u, s0, 2);
        s1 += __shfl_xor_sync(~0u, s1, 1); s1 += __shfl_xor_sync(~0u, s1, 2);
        const float rcp0 = 1.f / s0, rcp1 = 1.f / s1;

        float cs[16];
#pragma unroll
        for (int j = 0; j < 16; j++) {
            L0[j] *= rcp0; L1[j] *= rcp1;          // a values (exact fp32)
            cs[j] = L0[j] + L1[j];
        }
#pragma unroll
        for (int j = 0; j < 16; j++) {
            cs[j] += __shfl_xor_sync(~0u, cs[j], 4);
            cs[j] += __shfl_xor_sync(~0u, cs[j], 8);
            cs[j] += __shfl_xor_sync(~0u, cs[j], 16);
        }
        if (l < 4) {
#pragma unroll
            for (int nf = 0; nf < 8; nf++) {
                const int col = nf * 8 + c2;
                atomicAdd(&sAsum[col],     cs[2 * nf]);        // smem atomics only
                atomicAdd(&sAsum[col + 1], cs[2 * nf + 1]);
            }
        }
#pragma unroll
        for (int nf = 0; nf < 8; nf++) {
            const int col = nf * 8 + c2;
            *(__nv_bfloat162*)&as[r0][col] =
                __floats2bfloat162_rn(L0[2 * nf] * inv0, L0[2 * nf + 1] * inv0);
            *(__nv_bfloat162*)&as[r1][col] =
                __floats2bfloat162_rn(L1[2 * nf] * inv1, L1[2 * nf + 1] * inv1);
        }
    }
    __syncthreads();
    if (tid < 64)  // plain (non-atomic) asum partial store
        g_asump[(tc * 8 + n) * 64 + tid] = sAsum[tid];

    // ---- Phase 4: VLAD MMA  C[64 k x 512 d] = a'^T (64x128) * xs (128x512) ----
    {
        const int wm  = (w & 3) * 16;        // cluster rows
        const int wn2 = (w >> 2) * 64;       // d sub-column within 128-wide tile
        const int at_row = ((l >> 4) * 8) + (l & 7);
        const int at_col = ((l >> 3) & 1) * 8;
        const int bt_row = (((l >> 3) & 1) * 8) + (l & 7);
        const int bt_col = (l >> 4) * 8;

        uint32_t ar[8][4];
#pragma unroll
        for (int ts = 0; ts < 8; ts++)
            ldsm_x4t(smem_u32(&as[ts * 16 + at_row][wm + at_col]),
                     ar[ts][0], ar[ts][1], ar[ts][2], ar[ts][3]);

        const int g  = l >> 2;
        const int c2 = (l & 3) * 2;
        const size_t kn0 = (size_t)n * 64;

#pragma unroll
        for (int dt = 0; dt < 4; dt++) {
            const int dbase = dt * 128 + wn2;
            float vacc[8][4];
#pragma unroll
            for (int i = 0; i < 8; i++)
#pragma unroll
                for (int j = 0; j < 4; j++) vacc[i][j] = 0.f;

#pragma unroll
            for (int ts = 0; ts < 8; ts++) {
                const int kt = ts * 16;
#pragma unroll
                for (int nf2 = 0; nf2 < 4; nf2++) {
                    uint32_t b0, b1, b2, b3;
                    ldsm_x4t(smem_u32(&xs[kt + bt_row][dbase + nf2 * 16 + bt_col]),
                             b0, b1, b2, b3);
                    mma16816(vacc[nf2 * 2],     ar[ts][0], ar[ts][1], ar[ts][2], ar[ts][3], b0, b1);
                    mma16816(vacc[nf2 * 2 + 1], ar[ts][0], ar[ts][1], ar[ts][2], ar[ts][3], b2, b3);
                }
            }
            // bf16 partial stores, layout [n][k][p=tc][d]
#pragma unroll
            for (int nf = 0; nf < 8; nf++) {
                const int col = dbase + nf * 8 + c2;
                *(__nv_bfloat162*)&g_vpb[(((kn0 + wm + g) * 16 + tc) << 9) + col] =
                    __floats2bfloat162_rn(vacc[nf][0], vacc[nf][1]);
                *(__nv_bfloat162*)&g_vpb[(((kn0 + wm + g + 8) * 16 + tc) << 9) + col] =
                    __floats2bfloat162_rn(vacc[nf][2], vacc[nf][3]);
            }
        }
    }

    // ---- signal: this tc-chunk's partials for n are globally visible ----
    __threadfence();
    __syncthreads();
    if (tid == 0) atomicAdd(&g_cnt[n], 1);

    // ==================== CONSUMER (same block) ====================
    // Block (tc,n) finalizes rows n*64 + tc*4 .. +3 once all 16 chunks of n
    // have arrived. All 128 blocks are resident (single wave) -> no deadlock.
    __shared__ float wsum[4][2];
    __shared__ float s_sh[4];

    if (tid == 0) {
        while (atomicAdd(&g_cnt[n], 0) < 16) __nanosleep(64);
    }
    __syncthreads();
    __threadfence();   // acquire: order partial reads after the counter read

    const int rb  = w >> 1;          // row within group (0..3)
    const int wr  = w & 1;           // warp within row (0..1)
    const int row = n * 64 + tc * 4 + rb;
    const int k   = tc * 4 + rb;

    // asum reduce (16 partials) on the first warp of each row
    if (wr == 0) {
        float a = (l < 16) ? g_asump[(l * 8 + n) * 64 + k] : 0.f;
        a += __shfl_xor_sync(~0u, a, 8);
        a += __shfl_xor_sync(~0u, a, 4);
        a += __shfl_xor_sync(~0u, a, 2);
        a += __shfl_xor_sync(~0u, a, 1);
        if (l == 0) s_sh[rb] = a;
    }

    const int ei = wr * 32 + l;                       // uint4 index (8 bf16)
    const uint4* base = (const uint4*)(g_vpb + (size_t)row * 16 * 512);
    uint4 d[16];
#pragma unroll
    for (int p = 0; p < 16; p++) d[p] = base[p * 64 + ei];

    // packed bf16x2 pairwise reduction tree
#pragma unroll
    for (int step = 8; step > 0; step >>= 1)
#pragma unroll
        for (int p = 0; p < 8; p++) {
            if (p < step) {
                d[p].x = bf22u(__hadd2(u2bf2(d[p].x), u2bf2(d[p + step].x)));
                d[p].y = bf22u(__hadd2(u2bf2(d[p].y), u2bf2(d[p + step].y)));
                d[p].z = bf22u(__hadd2(u2bf2(d[p].z), u2bf2(d[p + step].z)));
                d[p].w = bf22u(__hadd2(u2bf2(d[p].w), u2bf2(d[p + step].w)));
            }
        }

    float v[8];
    {
        const float2 f0 = __bfloat1622float2(u2bf2(d[0].x));
        const float2 f1 = __bfloat1622float2(u2bf2(d[0].y));
        const float2 f2 = __bfloat1622float2(u2bf2(d[0].z));
        const float2 f3 = __bfloat1622float2(u2bf2(d[0].w));
        v[0] = f0.x; v[1] = f0.y; v[2] = f1.x; v[3] = f1.y;
        v[4] = f2.x; v[5] = f2.y; v[6] = f3.x; v[7] = f3.y;
    }

    __syncthreads();
    const float s = s_sh[rb];
    const float4 c0 = *(const float4*)(cent + (size_t)k * 512 + ei * 8);
    const float4 c1 = *(const float4*)(cent + (size_t)k * 512 + ei * 8 + 4);
    v[0] -= s * c0.x; v[1] -= s * c0.y; v[2] -= s * c0.z; v[3] -= s * c0.w;
    v[4] -= s * c1.x; v[5] -= s * c1.y; v[6] -= s * c1.z; v[7] -= s * c1.w;

    float sq2 = 0.f;
#pragma unroll
    for (int j = 0; j < 8; j++) sq2 += v[j] * v[j];
    sq2 += __shfl_xor_sync(~0u, sq2, 16);
    sq2 += __shfl_xor_sync(~0u, sq2, 8);
    sq2 += __shfl_xor_sync(~0u, sq2, 4);
    sq2 += __shfl_xor_sync(~0u, sq2, 2);
    sq2 += __shfl_xor_sync(~0u, sq2, 1);
    if (l == 0) wsum[rb][wr] = sq2;
    __syncthreads();

    const float tot = wsum[rb][0] + wsum[rb][1];
    const float inv = 0.125f / fmaxf(sqrtf(tot), EPSF);  // intra-norm * global 1/8

    float4 o0, o1;
    o0.x = v[0] * inv; o0.y = v[1] * inv; o0.z = v[2] * inv; o0.w = v[3] * inv;
    o1.x = v[4] * inv; o1.y = v[5] * inv; o1.z = v[6] * inv; o1.w = v[7] * inv;
    float* op = out + (size_t)row * 512 + ei * 8;
    *(float4*)op       = o0;
    *(float4*)(op + 4) = o1;

    // self-reset counters for the next (graph-replayed) call
    __syncthreads();
    if (tid == 0) {
        int old = atomicAdd(&g_done[n], 1);
        if (old == 15) {            // last finalizing block of this n
            atomicExch(&g_done[n], 0);
            atomicExch(&g_cnt[n], 0);
        }
    }
}

// ---------------------------------------------------------------------------
extern "C" void kernel_launch(void* const* d_in, const int* in_sizes, int n_in,
                              void* d_out, int out_size) {
    const float* x    = (const float*)d_in[0];   // [8,2048,512]
    const float* W    = (const float*)d_in[1];   // [64,512]
    const float* b    = (const float*)d_in[2];   // [64]
    const float* cent = (const float*)d_in[3];   // [64,512]
    float* out = (float*)d_out;                  // [8, 64*512]

    cudaFuncSetAttribute(netvlad_kernel,
                         cudaFuncAttributeMaxDynamicSharedMemorySize,
                         (int)SMEM_BYTES);

    netvlad_kernel<<<128, 256, SMEM_BYTES>>>(x, W, b, cent, out);
}